// round 2
// baseline (speedup 1.0000x reference)
#include <cuda_runtime.h>
#include <math.h>

// ---------------- problem constants ----------------
#define B      16
#define CIN    15          // C*T = 3*5
#define HIN    384
#define GH     192         // gating conv out spatial
#define PH     96          // pooled / expert spatial
#define NEXP   3
#define NOUT_CH 6
#define N_OUT  (B*NOUT_CH*PH*PH)   // 884736

typedef unsigned long long ull;

// ---------------- packed f32x2 helpers (sm_103a FFMA2) ----------------
__device__ __forceinline__ ull pack2(float lo, float hi) {
    ull r;
    asm("mov.b64 %0, {%1,%2};" : "=l"(r) : "f"(lo), "f"(hi));
    return r;
}
__device__ __forceinline__ void unpack2(ull v, float& lo, float& hi) {
    asm("mov.b64 {%0,%1}, %2;" : "=f"(lo), "=f"(hi) : "l"(v));
}
__device__ __forceinline__ ull fma2(ull a, ull b, ull c) {
    ull d;
    asm("fma.rn.f32x2 %0, %1, %2, %3;" : "=l"(d) : "l"(a), "l"(b), "l"(c));
    return d;
}

// ---------------- device scratch (allocation-free rule: __device__ globals) ----
__device__ float g_gate[B*64*GH*GH];      // gating conv output  (151 MB)
__device__ float g_feat[B*64];
__device__ int   g_idx[B];
__device__ float g_y1[B*64*PH*PH];        // expert conv1 out    (37.7 MB)
__device__ float g_y2[B*384*PH*PH];       // head conv1 out      (226 MB)

// =====================================================================
// Kernel 1: gating conv 7x7 stride2 pad3  (15 -> 64) + BN + ReLU
// tile 16x16 outputs, 256 thr: 4 oc-groups x 64 px-threads (2x2 px, 16 oc each)
// f32x2: horizontal pixel pair packed per accumulator, dup weights in smem
// =====================================================================
__global__ void gating_conv(const float* __restrict__ x,
                            const float* __restrict__ w,
                            const float* __restrict__ gamma,
                            const float* __restrict__ beta,
                            const float* __restrict__ mean,
                            const float* __restrict__ var)
{
    __shared__ float  in_s[37*37];
    __shared__ float2 w_s2[49*64];    // {w,w} duplicated

    const int b   = blockIdx.z;
    const int oh0 = blockIdx.y * 16;
    const int ow0 = blockIdx.x * 16;
    const int ih0 = oh0*2 - 3;
    const int iw0 = ow0*2 - 3;
    const int tid = threadIdx.x;
    const int ocg = tid >> 6;          // 0..3
    const int p   = tid & 63;
    const int py  = p >> 3;            // 0..7
    const int px  = p & 7;             // 0..7

    ull acc0[16], acc1[16];
    #pragma unroll
    for (int j = 0; j < 16; j++) { acc0[j] = 0ull; acc1[j] = 0ull; }

    const float* xb = x + (size_t)b * CIN * HIN * HIN;

    for (int ic = 0; ic < CIN; ic++) {
        __syncthreads();
        const float* xc = xb + (size_t)ic * HIN * HIN;
        for (int i = tid; i < 37*37; i += 256) {
            int r = i / 37, c = i - r*37;
            int gh = ih0 + r, gw = iw0 + c;
            float v = 0.f;
            if ((unsigned)gh < (unsigned)HIN && (unsigned)gw < (unsigned)HIN)
                v = xc[gh*HIN + gw];
            in_s[i] = v;
        }
        for (int i = tid; i < 3136; i += 256) {       // w_s2[tap*64+oc] = {w,w}
            int tap = i >> 6, oc = i & 63;
            float v = w[oc*735 + ic*49 + tap];
            w_s2[i] = make_float2(v, v);
        }
        __syncthreads();

        for (int kh = 0; kh < 7; kh++) {
            #pragma unroll
            for (int kw = 0; kw < 7; kw++) {
                const int tap = kh*7 + kw;
                const float* r0 = &in_s[(4*py + kh)*37 + 4*px + kw];
                const float* r1 = r0 + 2*37;
                const ull p0 = pack2(r0[0], r0[2]);
                const ull p1 = pack2(r1[0], r1[2]);
                const ull* wp = (const ull*)&w_s2[tap*64 + ocg*16];
                #pragma unroll
                for (int j = 0; j < 16; j++) {
                    const ull wv = wp[j];
                    acc0[j] = fma2(p0, wv, acc0[j]);
                    acc1[j] = fma2(p1, wv, acc1[j]);
                }
            }
        }
    }

    const int oh = oh0 + 2*py;
    const int ow = ow0 + 2*px;
    #pragma unroll
    for (int j = 0; j < 16; j++) {
        const int oc = ocg*16 + j;
        const float inv  = gamma[oc] * rsqrtf(var[oc] + 1e-5f);
        const float bia  = beta[oc] - mean[oc]*inv;
        float a0, a1, a2, a3;
        unpack2(acc0[j], a0, a1);
        unpack2(acc1[j], a2, a3);
        float* o = g_gate + (((size_t)b*64 + oc)*GH + oh)*GH + ow;
        o[0]      = fmaxf(a0*inv + bia, 0.f);
        o[1]      = fmaxf(a1*inv + bia, 0.f);
        o[GH]     = fmaxf(a2*inv + bia, 0.f);
        o[GH + 1] = fmaxf(a3*inv + bia, 0.f);
    }
}

// =====================================================================
// Kernel 2: maxpool 3x3 s2 p1 (192->96) + spatial mean  -> g_feat[b][c]
// =====================================================================
__global__ void pool_mean()
{
    const int bc = blockIdx.x;                 // b*64 + c
    const float* src = g_gate + (size_t)bc * GH * GH;
    const int tid = threadIdx.x;
    float sum = 0.f;
    for (int p = tid; p < PH*PH; p += 256) {
        int ph = p / PH, pw = p - ph*PH;
        float m = -1e30f;
        #pragma unroll
        for (int r = 0; r < 3; r++) {
            int ih = 2*ph - 1 + r;
            if ((unsigned)ih >= (unsigned)GH) continue;
            #pragma unroll
            for (int c = 0; c < 3; c++) {
                int iw = 2*pw - 1 + c;
                if ((unsigned)iw >= (unsigned)GH) continue;
                m = fmaxf(m, src[ih*GH + iw]);
            }
        }
        sum += m;
    }
    __shared__ float red[256];
    red[tid] = sum;
    __syncthreads();
    for (int s = 128; s > 0; s >>= 1) {
        if (tid < s) red[tid] += red[tid + s];
        __syncthreads();
    }
    if (tid == 0) g_feat[bc] = red[0] / (float)(PH*PH);
}

// =====================================================================
// Kernel 3: logits, argmax -> g_idx, aux loss -> d_out[N_OUT]
// =====================================================================
__global__ void gate_head(const float* __restrict__ fcw,
                          const float* __restrict__ fcb,
                          float* __restrict__ out, int out_size)
{
    __shared__ float lg[B][NEXP];
    __shared__ float proxy[NEXP];
    __shared__ int   cnt[NEXP];
    const int t = threadIdx.x;

    if (t < NEXP) { proxy[t] = 0.f; cnt[t] = 0; }
    if (t < B*NEXP) {
        int b = t / NEXP, e = t - b*NEXP;
        float s = fcb[e];
        const float* f = g_feat + b*64;
        const float* wr = fcw + e*64;
        for (int c = 0; c < 64; c++) s += f[c]*wr[c];
        lg[b][e] = s;
    }
    __syncthreads();
    if (t < B) {
        float l0 = lg[t][0], l1 = lg[t][1], l2 = lg[t][2];
        int am = 0; float bm = l0;
        if (l1 > bm) { bm = l1; am = 1; }
        if (l2 > bm) { bm = l2; am = 2; }
        g_idx[t] = am;
        atomicAdd(&cnt[am], 1);
        float m = bm;
        float e0 = expf(l0 - m), e1 = expf(l1 - m), e2 = expf(l2 - m);
        float s = e0 + e1 + e2;
        atomicAdd(&proxy[0], e0/s);
        atomicAdd(&proxy[1], e1/s);
        atomicAdd(&proxy[2], e2/s);
    }
    __syncthreads();
    if (t == 0 && out_size > N_OUT) {
        float aux = 0.f;
        for (int e = 0; e < NEXP; e++)
            aux += ((float)cnt[e] / (float)B) * (proxy[e] / (float)B);
        out[N_OUT] = 0.01f * (aux * (float)NEXP);
    }
}

// =====================================================================
// Kernel 4: selected-expert conv1 7x7 stride4 pad3 (15->64) + bias + ReLU
// tile 16x16 outputs; patch 67x67 per ic; f32x2 packed
// =====================================================================
__global__ void expert_conv1(const float* __restrict__ x,
                             const float* __restrict__ ew,
                             const float* __restrict__ eb)
{
    __shared__ float  in_s[67*67];
    __shared__ float2 w_s2[49*64];

    const int b   = blockIdx.z;
    const int e   = g_idx[b];
    const int oh0 = blockIdx.y * 16;
    const int ow0 = blockIdx.x * 16;
    const int ih0 = oh0*4 - 3;
    const int iw0 = ow0*4 - 3;
    const int tid = threadIdx.x;
    const int ocg = tid >> 6;
    const int p   = tid & 63;
    const int py  = p >> 3;
    const int px  = p & 7;

    ull acc0[16], acc1[16];
    #pragma unroll
    for (int j = 0; j < 16; j++) { acc0[j] = 0ull; acc1[j] = 0ull; }

    const float* xb = x + (size_t)b * CIN * HIN * HIN;
    const float* wb = ew + (size_t)e * 64 * 735;

    for (int ic = 0; ic < CIN; ic++) {
        __syncthreads();
        const float* xc = xb + (size_t)ic * HIN * HIN;
        for (int i = tid; i < 67*67; i += 256) {
            int r = i / 67, c = i - r*67;
            int gh = ih0 + r, gw = iw0 + c;
            float v = 0.f;
            if ((unsigned)gh < (unsigned)HIN && (unsigned)gw < (unsigned)HIN)
                v = xc[gh*HIN + gw];
            in_s[i] = v;
        }
        for (int i = tid; i < 3136; i += 256) {
            int tap = i >> 6, oc = i & 63;
            float v = wb[oc*735 + ic*49 + tap];
            w_s2[i] = make_float2(v, v);
        }
        __syncthreads();

        for (int kh = 0; kh < 7; kh++) {
            #pragma unroll
            for (int kw = 0; kw < 7; kw++) {
                const int tap = kh*7 + kw;
                const float* r0 = &in_s[(8*py + kh)*67 + 8*px + kw];
                const float* r1 = r0 + 4*67;
                const ull p0 = pack2(r0[0], r0[4]);
                const ull p1 = pack2(r1[0], r1[4]);
                const ull* wp = (const ull*)&w_s2[tap*64 + ocg*16];
                #pragma unroll
                for (int j = 0; j < 16; j++) {
                    const ull wv = wp[j];
                    acc0[j] = fma2(p0, wv, acc0[j]);
                    acc1[j] = fma2(p1, wv, acc1[j]);
                }
            }
        }
    }

    const int oh = oh0 + 2*py;
    const int ow = ow0 + 2*px;
    const float* bb = eb + e*64;
    #pragma unroll
    for (int j = 0; j < 16; j++) {
        const int oc = ocg*16 + j;
        const float bia = bb[oc];
        float a0, a1, a2, a3;
        unpack2(acc0[j], a0, a1);
        unpack2(acc1[j], a2, a3);
        float* o = g_y1 + (((size_t)b*64 + oc)*PH + oh)*PH + ow;
        o[0]      = fmaxf(a0 + bia, 0.f);
        o[1]      = fmaxf(a1 + bia, 0.f);
        o[PH]     = fmaxf(a2 + bia, 0.f);
        o[PH + 1] = fmaxf(a3 + bia, 0.f);
    }
}

// =====================================================================
// Kernel 5: head conv1 3x3 s1 p1 (64->384) + bias + ReLU (selected expert)
// tile 16x16 outputs, 64-oc block, ic chunks of 4; f32x2 packed
// gridDim.z = b*6 + ocb
// =====================================================================
__global__ void head_conv1(const float* __restrict__ hw1,
                           const float* __restrict__ hb1)
{
    __shared__ float  in_s[4*18*18];   // 1296
    __shared__ float2 w_s2[4*9*64];    // 2304 float2

    const int z   = blockIdx.z;
    const int b   = z / 6;
    const int ocb = z - b*6;          // 0..5 -> oc base = ocb*64
    const int e   = g_idx[b];
    const int oh0 = blockIdx.y * 16;
    const int ow0 = blockIdx.x * 16;
    const int tid = threadIdx.x;
    const int ocg = tid >> 6;
    const int p   = tid & 63;
    const int py  = p >> 3;
    const int px  = p & 7;

    ull acc0[16], acc1[16];
    #pragma unroll
    for (int j = 0; j < 16; j++) { acc0[j] = 0ull; acc1[j] = 0ull; }

    const float* yb = g_y1 + (size_t)b * 64 * PH * PH;
    const float* wb = hw1 + (size_t)e * 384 * 576 + (size_t)ocb * 64 * 576;

    for (int ic0 = 0; ic0 < 64; ic0 += 4) {
        __syncthreads();
        for (int i = tid; i < 4*324; i += 256) {
            int icc = i / 324;
            int r   = (i - icc*324) / 18;
            int c   = i - icc*324 - r*18;
            int gh  = oh0 - 1 + r, gw = ow0 - 1 + c;
            float v = 0.f;
            if ((unsigned)gh < (unsigned)PH && (unsigned)gw < (unsigned)PH)
                v = yb[((size_t)(ic0 + icc)*PH + gh)*PH + gw];
            in_s[i] = v;
        }
        for (int i = tid; i < 4*576; i += 256) {
            int icc = i / 576;
            int r   = i - icc*576;
            int tap = r >> 6, oc = r & 63;
            float v = wb[oc*576 + (ic0 + icc)*9 + tap];
            w_s2[i] = make_float2(v, v);
        }
        __syncthreads();

        #pragma unroll
        for (int icc = 0; icc < 4; icc++) {
            #pragma unroll
            for (int tap = 0; tap < 9; tap++) {
                const int kh = tap / 3, kw = tap - kh*3;
                const float* ip = &in_s[icc*324];
                const float* r0 = &ip[(2*py + kh)*18 + 2*px + kw];
                const float* r1 = r0 + 18;
                const ull p0 = pack2(r0[0], r0[1]);
                const ull p1 = pack2(r1[0], r1[1]);
                const ull* wp = (const ull*)&w_s2[icc*576 + tap*64 + ocg*16];
                #pragma unroll
                for (int j = 0; j < 16; j++) {
                    const ull wv = wp[j];
                    acc0[j] = fma2(p0, wv, acc0[j]);
                    acc1[j] = fma2(p1, wv, acc1[j]);
                }
            }
        }
    }

    const int oh = oh0 + 2*py;
    const int ow = ow0 + 2*px;
    #pragma unroll
    for (int j = 0; j < 16; j++) {
        const int oc = ocb*64 + ocg*16 + j;
        const float bia = hb1[e*384 + oc];
        float a0, a1, a2, a3;
        unpack2(acc0[j], a0, a1);
        unpack2(acc1[j], a2, a3);
        float* o = g_y2 + (((size_t)b*384 + oc)*PH + oh)*PH + ow;
        o[0]      = fmaxf(a0 + bia, 0.f);
        o[1]      = fmaxf(a1 + bia, 0.f);
        o[PH]     = fmaxf(a2 + bia, 0.f);
        o[PH + 1] = fmaxf(a3 + bia, 0.f);
    }
}

// =====================================================================
// Kernel 6: grouped 1x1 conv (384 -> 6, groups=3) + bias, gathered output
// grid (36, 3, 16)
// =====================================================================
__global__ void head_conv2(const float* __restrict__ hw2,
                           const float* __restrict__ hb2,
                           float* __restrict__ out)
{
    const int b = blockIdx.z;
    const int g = blockIdx.y;
    const int e = g_idx[b];
    const int tid = threadIdx.x;
    const int p = blockIdx.x * 256 + tid;

    __shared__ float w0s[128], w1s[128];
    if (tid < 128) {
        w0s[tid] = hw2[(e*6 + 2*g)    *128 + tid];
        w1s[tid] = hw2[(e*6 + 2*g + 1)*128 + tid];
    }
    __syncthreads();

    float a0 = hb2[e*6 + 2*g];
    float a1 = hb2[e*6 + 2*g + 1];
    const float* yp = g_y2 + ((size_t)b*384 + g*128) * (PH*PH) + p;
    #pragma unroll 8
    for (int ic = 0; ic < 128; ic++) {
        float v = yp[(size_t)ic * (PH*PH)];
        a0 += v * w0s[ic];
        a1 += v * w1s[ic];
    }
    out[((size_t)b*6 + 2*g)    *(PH*PH) + p] = a0;
    out[((size_t)b*6 + 2*g + 1)*(PH*PH) + p] = a1;
}

// =====================================================================
// launcher
// =====================================================================
extern "C" void kernel_launch(void* const* d_in, const int* in_sizes, int n_in,
                              void* d_out, int out_size)
{
    const float* x        = (const float*)d_in[0];
    const float* g_conv_w = (const float*)d_in[1];
    const float* g_gamma  = (const float*)d_in[2];
    const float* g_beta   = (const float*)d_in[3];
    const float* g_mean   = (const float*)d_in[4];
    const float* g_var    = (const float*)d_in[5];
    const float* g_fc_w   = (const float*)d_in[6];
    const float* g_fc_b   = (const float*)d_in[7];
    const float* e_conv1_w = (const float*)d_in[8];
    const float* e_conv1_b = (const float*)d_in[9];
    const float* e_head_w1 = (const float*)d_in[10];
    const float* e_head_b1 = (const float*)d_in[11];
    const float* e_head_w2 = (const float*)d_in[12];
    const float* e_head_b2 = (const float*)d_in[13];
    float* out = (float*)d_out;

    dim3 gconv(GH/16, GH/16, B);                 // 12,12,16
    gating_conv<<<gconv, 256>>>(x, g_conv_w, g_gamma, g_beta, g_mean, g_var);

    pool_mean<<<B*64, 256>>>();

    gate_head<<<1, 64>>>(g_fc_w, g_fc_b, out, out_size);

    dim3 gexp(PH/16, PH/16, B);                  // 6,6,16
    expert_conv1<<<gexp, 256>>>(x, e_conv1_w, e_conv1_b);

    dim3 ghead(PH/16, PH/16, B*6);               // 6,6,96
    head_conv1<<<ghead, 256>>>(e_head_w1, e_head_b1);

    dim3 gh2(PH*PH/256, 3, B);                   // 36,3,16
    head_conv2<<<gh2, 256>>>(e_head_w2, e_head_b2, out);
}

// round 4
// speedup vs baseline: 1.6692x; 1.6692x over previous
#include <cuda_runtime.h>
#include <cuda_bf16.h>
#include <math.h>
#include <stdint.h>

// ---------------- problem constants ----------------
#define B      16
#define CIN    15          // C*T = 3*5
#define HIN    384
#define GH     192         // gating conv out spatial
#define PH     96          // pooled / expert spatial
#define NEXP   3
#define NOUT_CH 6
#define N_OUT  (B*NOUT_CH*PH*PH)   // 884736

// ---------------- device scratch ----------------
__device__ float g_gate[B*64*GH*GH];
__device__ float g_feat[B*64];
__device__ int   g_idx[B];
__device__ float g_y1[B*64*PH*PH];              // [b][ic][96][96]
__device__ float g_y2[B*384*PH*PH];             // [b][oc][px]
__device__ __nv_bfloat16 g_wh[NEXP*9*384*64];   // [e][tap][oc][ic] hi
__device__ __nv_bfloat16 g_wl[NEXP*9*384*64];   // lo

// ---------------- helpers ----------------
__device__ __forceinline__ uint32_t smem_u32(const void* p) {
    uint32_t a;
    asm("{ .reg .u64 t; cvta.to.shared.u64 t, %1; cvt.u32.u64 %0, t; }" : "=r"(a) : "l"(p));
    return a;
}
#define SW128(x) ((x) ^ (((x) >> 3) & 0x70))

__device__ __forceinline__ uint32_t pkbf(__nv_bfloat16 a, __nv_bfloat16 b) {
    __nv_bfloat162 t = __halves2bfloat162(a, b);
    return *reinterpret_cast<uint32_t*>(&t);
}

#define LDSM4(r0, r1, r2, r3, a) \
    asm volatile("ldmatrix.sync.aligned.m8n8.x4.shared.b16 {%0,%1,%2,%3}, [%4];" \
        : "=r"(r0), "=r"(r1), "=r"(r2), "=r"(r3) : "r"(a))

#define MMA16816(d, a, b0, b1) \
    asm volatile("mma.sync.aligned.m16n8k16.row.col.f32.bf16.bf16.f32 " \
        "{%0,%1,%2,%3}, {%4,%5,%6,%7}, {%8,%9}, {%0,%1,%2,%3};" \
        : "+f"((d)[0]), "+f"((d)[1]), "+f"((d)[2]), "+f"((d)[3]) \
        : "r"((a)[0]), "r"((a)[1]), "r"((a)[2]), "r"((a)[3]), "r"(b0), "r"(b1))

// =====================================================================
// Kernel 1: gating conv 7x7 s2 p3 (15->64) + BN + ReLU   (R1 scalar, proven)
// =====================================================================
__global__ void gating_conv(const float* __restrict__ x,
                            const float* __restrict__ w,
                            const float* __restrict__ gamma,
                            const float* __restrict__ beta,
                            const float* __restrict__ mean,
                            const float* __restrict__ var)
{
    __shared__ float in_s[37*37];
    __shared__ float w_s[49*64];

    const int b   = blockIdx.z;
    const int oh0 = blockIdx.y * 16;
    const int ow0 = blockIdx.x * 16;
    const int ih0 = oh0*2 - 3;
    const int iw0 = ow0*2 - 3;
    const int tid = threadIdx.x;
    const int ocg = tid >> 6;
    const int p   = tid & 63;
    const int py  = p >> 3;
    const int px  = p & 7;

    float acc[4][16];
    #pragma unroll
    for (int s = 0; s < 4; s++)
        #pragma unroll
        for (int j = 0; j < 16; j++) acc[s][j] = 0.f;

    const float* xb = x + (size_t)b * CIN * HIN * HIN;

    for (int ic = 0; ic < CIN; ic++) {
        __syncthreads();
        const float* xc = xb + (size_t)ic * HIN * HIN;
        for (int i = tid; i < 37*37; i += 256) {
            int r = i / 37, c = i - r*37;
            int gh = ih0 + r, gw = iw0 + c;
            float v = 0.f;
            if ((unsigned)gh < (unsigned)HIN && (unsigned)gw < (unsigned)HIN)
                v = xc[gh*HIN + gw];
            in_s[i] = v;
        }
        for (int i = tid; i < 3136; i += 256) {
            int tap = i >> 6, oc = i & 63;
            w_s[i] = w[oc*735 + ic*49 + tap];
        }
        __syncthreads();

        for (int kh = 0; kh < 7; kh++) {
            #pragma unroll
            for (int kw = 0; kw < 7; kw++) {
                const int tap = kh*7 + kw;
                const float x00 = in_s[(4*py + kh)*37 + 4*px + kw];
                const float x01 = in_s[(4*py + kh)*37 + 4*px + 2 + kw];
                const float x10 = in_s[(4*py + 2 + kh)*37 + 4*px + kw];
                const float x11 = in_s[(4*py + 2 + kh)*37 + 4*px + 2 + kw];
                const float* wp = &w_s[tap*64 + ocg*16];
                #pragma unroll
                for (int j = 0; j < 16; j++) {
                    const float wv = wp[j];
                    acc[0][j] += x00*wv;
                    acc[1][j] += x01*wv;
                    acc[2][j] += x10*wv;
                    acc[3][j] += x11*wv;
                }
            }
        }
    }

    const int oh = oh0 + 2*py;
    const int ow = ow0 + 2*px;
    #pragma unroll
    for (int j = 0; j < 16; j++) {
        const int oc = ocg*16 + j;
        const float inv  = gamma[oc] * rsqrtf(var[oc] + 1e-5f);
        const float bia  = beta[oc] - mean[oc]*inv;
        float* o = g_gate + (((size_t)b*64 + oc)*GH + oh)*GH + ow;
        o[0]      = fmaxf(acc[0][j]*inv + bia, 0.f);
        o[1]      = fmaxf(acc[1][j]*inv + bia, 0.f);
        o[GH]     = fmaxf(acc[2][j]*inv + bia, 0.f);
        o[GH + 1] = fmaxf(acc[3][j]*inv + bia, 0.f);
    }
}

// =====================================================================
// Kernel 2: maxpool 3x3 s2 p1 + spatial mean
// =====================================================================
__global__ void pool_mean()
{
    const int bc = blockIdx.x;
    const float* src = g_gate + (size_t)bc * GH * GH;
    const int tid = threadIdx.x;
    float sum = 0.f;
    for (int p = tid; p < PH*PH; p += 256) {
        int ph = p / PH, pw = p - ph*PH;
        float m = -1e30f;
        #pragma unroll
        for (int r = 0; r < 3; r++) {
            int ih = 2*ph - 1 + r;
            if ((unsigned)ih >= (unsigned)GH) continue;
            #pragma unroll
            for (int c = 0; c < 3; c++) {
                int iw = 2*pw - 1 + c;
                if ((unsigned)iw >= (unsigned)GH) continue;
                m = fmaxf(m, src[ih*GH + iw]);
            }
        }
        sum += m;
    }
    __shared__ float red[256];
    red[tid] = sum;
    __syncthreads();
    for (int s = 128; s > 0; s >>= 1) {
        if (tid < s) red[tid] += red[tid + s];
        __syncthreads();
    }
    if (tid == 0) g_feat[bc] = red[0] / (float)(PH*PH);
}

// =====================================================================
// Kernel 3: logits, argmax, aux loss
// =====================================================================
__global__ void gate_head(const float* __restrict__ fcw,
                          const float* __restrict__ fcb,
                          float* __restrict__ out, int out_size)
{
    __shared__ float lg[B][NEXP];
    __shared__ float proxy[NEXP];
    __shared__ int   cnt[NEXP];
    const int t = threadIdx.x;

    if (t < NEXP) { proxy[t] = 0.f; cnt[t] = 0; }
    if (t < B*NEXP) {
        int b = t / NEXP, e = t - b*NEXP;
        float s = fcb[e];
        const float* f = g_feat + b*64;
        const float* wr = fcw + e*64;
        for (int c = 0; c < 64; c++) s += f[c]*wr[c];
        lg[b][e] = s;
    }
    __syncthreads();
    if (t < B) {
        float l0 = lg[t][0], l1 = lg[t][1], l2 = lg[t][2];
        int am = 0; float bm = l0;
        if (l1 > bm) { bm = l1; am = 1; }
        if (l2 > bm) { bm = l2; am = 2; }
        g_idx[t] = am;
        atomicAdd(&cnt[am], 1);
        float m = bm;
        float e0 = expf(l0 - m), e1 = expf(l1 - m), e2 = expf(l2 - m);
        float s = e0 + e1 + e2;
        atomicAdd(&proxy[0], e0/s);
        atomicAdd(&proxy[1], e1/s);
        atomicAdd(&proxy[2], e2/s);
    }
    __syncthreads();
    if (t == 0 && out_size > N_OUT) {
        float aux = 0.f;
        for (int e = 0; e < NEXP; e++)
            aux += ((float)cnt[e] / (float)B) * (proxy[e] / (float)B);
        out[N_OUT] = 0.01f * (aux * (float)NEXP);
    }
}

// =====================================================================
// Kernel 4: expert conv1 7x7 s4 p3 (15->64) + bias + ReLU  (R1 scalar)
// =====================================================================
__global__ void expert_conv1(const float* __restrict__ x,
                             const float* __restrict__ ew,
                             const float* __restrict__ eb)
{
    __shared__ float in_s[67*67];
    __shared__ float w_s[49*64];

    const int b   = blockIdx.z;
    const int e   = g_idx[b];
    const int oh0 = blockIdx.y * 16;
    const int ow0 = blockIdx.x * 16;
    const int ih0 = oh0*4 - 3;
    const int iw0 = ow0*4 - 3;
    const int tid = threadIdx.x;
    const int ocg = tid >> 6;
    const int p   = tid & 63;
    const int py  = p >> 3;
    const int px  = p & 7;

    float acc[4][16];
    #pragma unroll
    for (int s = 0; s < 4; s++)
        #pragma unroll
        for (int j = 0; j < 16; j++) acc[s][j] = 0.f;

    const float* xb = x + (size_t)b * CIN * HIN * HIN;
    const float* wb = ew + (size_t)e * 64 * 735;

    for (int ic = 0; ic < CIN; ic++) {
        __syncthreads();
        const float* xc = xb + (size_t)ic * HIN * HIN;
        for (int i = tid; i < 67*67; i += 256) {
            int r = i / 67, c = i - r*67;
            int gh = ih0 + r, gw = iw0 + c;
            float v = 0.f;
            if ((unsigned)gh < (unsigned)HIN && (unsigned)gw < (unsigned)HIN)
                v = xc[gh*HIN + gw];
            in_s[i] = v;
        }
        for (int i = tid; i < 3136; i += 256) {
            int tap = i >> 6, oc = i & 63;
            w_s[i] = wb[oc*735 + ic*49 + tap];
        }
        __syncthreads();

        for (int kh = 0; kh < 7; kh++) {
            #pragma unroll
            for (int kw = 0; kw < 7; kw++) {
                const int tap = kh*7 + kw;
                const float x00 = in_s[(8*py + kh)*67 + 8*px + kw];
                const float x01 = in_s[(8*py + kh)*67 + 8*px + 4 + kw];
                const float x10 = in_s[(8*py + 4 + kh)*67 + 8*px + kw];
                const float x11 = in_s[(8*py + 4 + kh)*67 + 8*px + 4 + kw];
                const float* wp = &w_s[tap*64 + ocg*16];
                #pragma unroll
                for (int j = 0; j < 16; j++) {
                    const float wv = wp[j];
                    acc[0][j] += x00*wv;
                    acc[1][j] += x01*wv;
                    acc[2][j] += x10*wv;
                    acc[3][j] += x11*wv;
                }
            }
        }
    }

    const int oh = oh0 + 2*py;
    const int ow = ow0 + 2*px;
    const float* bb = eb + e*64;
    #pragma unroll
    for (int j = 0; j < 16; j++) {
        const int oc = ocg*16 + j;
        const float bia = bb[oc];
        float* o = g_y1 + (((size_t)b*64 + oc)*PH + oh)*PH + ow;
        o[0]      = fmaxf(acc[0][j] + bia, 0.f);
        o[1]      = fmaxf(acc[1][j] + bia, 0.f);
        o[PH]     = fmaxf(acc[2][j] + bia, 0.f);
        o[PH + 1] = fmaxf(acc[3][j] + bia, 0.f);
    }
}

// =====================================================================
// Kernel 4.5: convert head weights fp32 -> bf16 hi/lo, [e][tap][oc][ic]
// =====================================================================
__global__ void w_convert(const float* __restrict__ w)
{
    int i = blockIdx.x * 256 + threadIdx.x;
    if (i >= NEXP*384*64*9) return;
    int tap = i % 9;
    int r   = i / 9;
    int ic  = r % 64;
    int r2  = r / 64;
    int oc  = r2 % 384;
    int e   = r2 / 384;
    float v = w[i];
    __nv_bfloat16 h = __float2bfloat16_rn(v);
    float res = v - __bfloat162float(h);
    __nv_bfloat16 l = __float2bfloat16_rn(res);
    int dst = ((e*9 + tap)*384 + oc)*64 + ic;
    g_wh[dst] = h;
    g_wl[dst] = l;
}

// =====================================================================
// Kernel 5: head conv1 3x3 s1 p1 (64->384) via mma.sync bf16 split
// CTA tile: 128 oc x 128 px. 8 warps = 2(M) x 4(N); warp = 64 oc x 32 px.
// smem: A_hi[0,16K) A_lo[16K,32K) B_hi[32K,48K) B_lo[48K,64K); epi reuse.
// =====================================================================
__global__ void __launch_bounds__(256)
head_conv1_mma(const float* __restrict__ hb1)
{
    extern __shared__ char smem[];
    const uint32_t sb = smem_u32(smem);
    const int tid = threadIdx.x;
    const int wid = tid >> 5, lid = tid & 31;
    const int b   = blockIdx.z;
    const int ocb = blockIdx.y;
    const int p0  = blockIdx.x * 128;
    const int e   = g_idx[b];

    const int warpM = wid >> 2, warpN = wid & 3;
    const int m0w = warpM * 64, n0w = warpN * 32;

    float acc[4][4][4];
    #pragma unroll
    for (int mt = 0; mt < 4; mt++)
        #pragma unroll
        for (int nt = 0; nt < 4; nt++)
            #pragma unroll
            for (int q = 0; q < 4; q++) acc[mt][nt][q] = 0.f;

    // B-builder mapping
    const int n = tid & 127;
    const int g = tid >> 7;
    const int p = p0 + n;
    const int pr = p / 96;
    const int pc = p - pr*96;
    const float* y1b = g_y1 + (size_t)b * 64 * PH*PH;

    // ldmatrix per-lane geometry
    const int rr  = lid & 7;
    const int sel = lid >> 3;

    for (int tap = 0; tap < 9; tap++) {
        const int kh = tap / 3, kw = tap - 3*(tap/3);
        __syncthreads();

        // ---- stage A: 128 oc x 64 ic, hi+lo (2048 x uint4)
        {
            const __nv_bfloat16* whb = g_wh + ((size_t)((e*9 + tap)*384 + ocb*128))*64;
            const __nv_bfloat16* wlb = g_wl + ((size_t)((e*9 + tap)*384 + ocb*128))*64;
            #pragma unroll
            for (int it = 0; it < 8; it++) {
                int idx = it*256 + tid;        // 0..2047
                int s   = idx >> 10;
                int r   = idx & 1023;
                int oc  = r >> 3;
                int ch  = r & 7;
                const __nv_bfloat16* src = (s ? wlb : whb) + oc*64 + ch*8;
                uint4 v = *(const uint4*)src;
                *(uint4*)(smem + s*16384 + SW128((uint32_t)(oc*128 + ch*16))) = v;
            }
        }

        // ---- build B: 128 px x 64 ic, split hi/lo
        {
            const int ri = pr + kh - 1, ci = pc + kw - 1;
            const bool ok = ((unsigned)ri < 96u) && ((unsigned)ci < 96u);
            const float* yq = y1b + (size_t)ri*96 + ci;
            #pragma unroll
            for (int j = 0; j < 4; j++) {
                const int ic0 = g*32 + j*8;
                float v[8];
                #pragma unroll
                for (int u = 0; u < 8; u++)
                    v[u] = ok ? __ldg(yq + (size_t)(ic0 + u) * (PH*PH)) : 0.f;
                __nv_bfloat16 h[8];
                uint32_t hp[4], lp[4];
                #pragma unroll
                for (int u = 0; u < 8; u++) h[u] = __float2bfloat16_rn(v[u]);
                #pragma unroll
                for (int u = 0; u < 4; u++) hp[u] = pkbf(h[2*u], h[2*u+1]);
                #pragma unroll
                for (int u = 0; u < 8; u += 2) {
                    __nv_bfloat16 l0 = __float2bfloat16_rn(v[u]   - __bfloat162float(h[u]));
                    __nv_bfloat16 l1 = __float2bfloat16_rn(v[u+1] - __bfloat162float(h[u+1]));
                    lp[u>>1] = pkbf(l0, l1);
                }
                const uint32_t off = SW128((uint32_t)(n*128 + ic0*2));
                *(uint4*)(smem + 32768 + off) = make_uint4(hp[0], hp[1], hp[2], hp[3]);
                *(uint4*)(smem + 49152 + off) = make_uint4(lp[0], lp[1], lp[2], lp[3]);
            }
        }
        __syncthreads();

        // ---- MMA over 4 K-chunks of 16
        #pragma unroll
        for (int kc = 0; kc < 4; kc++) {
            const int k0b = kc*32;   // bytes

            uint32_t ah[4][4], al[4][4];
            {
                const int arow = m0w + (sel & 1)*8 + rr;
                const int akb  = k0b + ((sel >> 1)*8)*2;
                #pragma unroll
                for (int mt = 0; mt < 4; mt++) {
                    uint32_t off = SW128((uint32_t)((arow + mt*16)*128 + akb));
                    LDSM4(ah[mt][0], ah[mt][1], ah[mt][2], ah[mt][3], sb + off);
                    LDSM4(al[mt][0], al[mt][1], al[mt][2], al[mt][3], sb + 16384 + off);
                }
            }

            uint32_t bh[4][2], bl[4][2];
            {
                const int brow = n0w + (sel >> 1)*8 + rr;
                const int bkb  = k0b + ((sel & 1)*8)*2;
                #pragma unroll
                for (int pair = 0; pair < 2; pair++) {
                    uint32_t off = SW128((uint32_t)((brow + pair*16)*128 + bkb));
                    LDSM4(bh[pair*2][0], bh[pair*2][1], bh[pair*2+1][0], bh[pair*2+1][1],
                          sb + 32768 + off);
                    LDSM4(bl[pair*2][0], bl[pair*2][1], bl[pair*2+1][0], bl[pair*2+1][1],
                          sb + 49152 + off);
                }
            }

            #pragma unroll
            for (int mt = 0; mt < 4; mt++)
                #pragma unroll
                for (int nt = 0; nt < 4; nt++) {
                    MMA16816(acc[mt][nt], ah[mt], bh[nt][0], bh[nt][1]);
                    MMA16816(acc[mt][nt], ah[mt], bl[nt][0], bl[nt][1]);
                    MMA16816(acc[mt][nt], al[mt], bh[nt][0], bh[nt][1]);
                }
        }
    }

    // ---- epilogue via smem (reuse stage area): [128 oc][128 px] fp32
    __syncthreads();
    float* epi = (float*)smem;
    {
        const int r  = lid >> 2;
        const int cc = (lid & 3) * 2;
        #pragma unroll
        for (int mt = 0; mt < 4; mt++)
            #pragma unroll
            for (int nt = 0; nt < 4; nt++) {
                const int m  = m0w + mt*16 + r;
                const int nn = n0w + nt*8 + cc;
                epi[m*128 + nn]       = acc[mt][nt][0];
                epi[m*128 + nn + 1]   = acc[mt][nt][1];
                epi[(m+8)*128 + nn]     = acc[mt][nt][2];
                epi[(m+8)*128 + nn + 1] = acc[mt][nt][3];
            }
    }
    __syncthreads();
    {
        const float* bb = hb1 + e*384 + ocb*128;
        #pragma unroll
        for (int it = 0; it < 16; it++) {
            int i  = it*256 + tid;        // uint4 index 0..4095
            int oc = i >> 5;
            int cx = (i & 31) * 4;
            float4 v = *(float4*)&epi[oc*128 + cx];
            float bias = bb[oc];
            v.x = fmaxf(v.x + bias, 0.f);
            v.y = fmaxf(v.y + bias, 0.f);
            v.z = fmaxf(v.z + bias, 0.f);
            v.w = fmaxf(v.w + bias, 0.f);
            *(float4*)&g_y2[((size_t)(b*384 + ocb*128 + oc))*(PH*PH) + p0 + cx] = v;
        }
    }
}

// =====================================================================
// Kernel 6: grouped 1x1 conv (384 -> 6, groups=3) + bias (R1, oc-major y2)
// =====================================================================
__global__ void head_conv2(const float* __restrict__ hw2,
                           const float* __restrict__ hb2,
                           float* __restrict__ out)
{
    const int b = blockIdx.z;
    const int g = blockIdx.y;
    const int e = g_idx[b];
    const int tid = threadIdx.x;
    const int p = blockIdx.x * 256 + tid;

    __shared__ float w0s[128], w1s[128];
    if (tid < 128) {
        w0s[tid] = hw2[(e*6 + 2*g)    *128 + tid];
        w1s[tid] = hw2[(e*6 + 2*g + 1)*128 + tid];
    }
    __syncthreads();

    float a0 = hb2[e*6 + 2*g];
    float a1 = hb2[e*6 + 2*g + 1];
    const float* yp = g_y2 + ((size_t)b*384 + g*128) * (PH*PH) + p;
    #pragma unroll 8
    for (int ic = 0; ic < 128; ic++) {
        float v = yp[(size_t)ic * (PH*PH)];
        a0 += v * w0s[ic];
        a1 += v * w1s[ic];
    }
    out[((size_t)b*6 + 2*g)    *(PH*PH) + p] = a0;
    out[((size_t)b*6 + 2*g + 1)*(PH*PH) + p] = a1;
}

// =====================================================================
// launcher
// =====================================================================
extern "C" void kernel_launch(void* const* d_in, const int* in_sizes, int n_in,
                              void* d_out, int out_size)
{
    const float* x        = (const float*)d_in[0];
    const float* g_conv_w = (const float*)d_in[1];
    const float* g_gamma  = (const float*)d_in[2];
    const float* g_beta   = (const float*)d_in[3];
    const float* g_mean   = (const float*)d_in[4];
    const float* g_var    = (const float*)d_in[5];
    const float* g_fc_w   = (const float*)d_in[6];
    const float* g_fc_b   = (const float*)d_in[7];
    const float* e_conv1_w = (const float*)d_in[8];
    const float* e_conv1_b = (const float*)d_in[9];
    const float* e_head_w1 = (const float*)d_in[10];
    const float* e_head_b1 = (const float*)d_in[11];
    const float* e_head_w2 = (const float*)d_in[12];
    const float* e_head_b2 = (const float*)d_in[13];
    float* out = (float*)d_out;

    cudaFuncSetAttribute(head_conv1_mma,
                         cudaFuncAttributeMaxDynamicSharedMemorySize, 65536);

    dim3 gconv(GH/16, GH/16, B);
    gating_conv<<<gconv, 256>>>(x, g_conv_w, g_gamma, g_beta, g_mean, g_var);

    pool_mean<<<B*64, 256>>>();

    gate_head<<<1, 64>>>(g_fc_w, g_fc_b, out, out_size);

    w_convert<<<(NEXP*384*64*9 + 255)/256, 256>>>(e_head_w1);

    dim3 gexp(PH/16, PH/16, B);
    expert_conv1<<<gexp, 256>>>(x, e_conv1_w, e_conv1_b);

    dim3 ghead(PH*PH/128, 3, B);                 // 72, 3, 16
    head_conv1_mma<<<ghead, 256, 65536>>>(e_head_b1);

    dim3 gh2(PH*PH/256, 3, B);                   // 36, 3, 16
    head_conv2<<<gh2, 256>>>(e_head_w2, e_head_b2, out);
}

// round 5
// speedup vs baseline: 3.2389x; 1.9404x over previous
#include <cuda_runtime.h>
#include <cuda_bf16.h>
#include <math.h>
#include <stdint.h>

// ---------------- problem constants ----------------
#define B      16
#define CIN    15          // C*T = 3*5
#define HIN    384
#define GH     192         // gating conv out spatial
#define PH     96          // pooled / expert spatial
#define NEXP   3
#define N_OUT  (B*6*PH*PH)   // 884736

// ---------------- device scratch ----------------
__device__ float g_gate[B*64*GH*GH];
__device__ float g_feat[B*64];
__device__ int   g_idx[B];
__device__ float g_y1[B*64*PH*PH];              // [b][ic][96][96]
__device__ float g_y2[B*384*PH*PH];             // [b][oc][px]
__device__ __nv_bfloat16 g_wh[NEXP*9*384*64];   // head w1 hi [e][tap][oc][ic]
__device__ __nv_bfloat16 g_wl[NEXP*9*384*64];   // lo
__device__ __nv_bfloat16 g_gwh[49*64*16];       // gating w hi [tap][oc][ic16]
__device__ __nv_bfloat16 g_gwl[49*64*16];
__device__ __nv_bfloat16 g_ewh[NEXP*49*64*16];  // expert conv1 w hi [e][tap][oc][ic16]
__device__ __nv_bfloat16 g_ewl[NEXP*49*64*16];

// ---------------- helpers ----------------
__device__ __forceinline__ uint32_t smem_u32(const void* p) {
    uint32_t a;
    asm("{ .reg .u64 t; cvta.to.shared.u64 t, %1; cvt.u32.u64 %0, t; }" : "=r"(a) : "l"(p));
    return a;
}
#define SW128(x) ((x) ^ (((x) >> 3) & 0x70))

__device__ __forceinline__ uint32_t pkbf(__nv_bfloat16 a, __nv_bfloat16 b) {
    __nv_bfloat162 t = __halves2bfloat162(a, b);
    return *reinterpret_cast<uint32_t*>(&t);
}

#define LDSM4(r0, r1, r2, r3, a) \
    asm volatile("ldmatrix.sync.aligned.m8n8.x4.shared.b16 {%0,%1,%2,%3}, [%4];" \
        : "=r"(r0), "=r"(r1), "=r"(r2), "=r"(r3) : "r"(a))

#define MMA16816(d, a, b0, b1) \
    asm volatile("mma.sync.aligned.m16n8k16.row.col.f32.bf16.bf16.f32 " \
        "{%0,%1,%2,%3}, {%4,%5,%6,%7}, {%8,%9}, {%0,%1,%2,%3};" \
        : "+f"((d)[0]), "+f"((d)[1]), "+f"((d)[2]), "+f"((d)[3]) \
        : "r"((a)[0]), "r"((a)[1]), "r"((a)[2]), "r"((a)[3]), "r"(b0), "r"(b1))

// stage-area byte offsets for the 7x7 conv MMA kernels (48B rows, conflict-free)
#define SA_HI 0
#define SA_LO 3072
#define SB_HI 6144
#define SB_LO 18432
// epilogue reuses smem as float[64][256] = 65536 bytes

// =====================================================================
// weight split kernels
// =====================================================================
__global__ void gw_convert(const float* __restrict__ w)   // [64][15][7][7]
{
    int i = blockIdx.x * 256 + threadIdx.x;
    if (i >= 49*64*16) return;
    int ic = i & 15, oc = (i >> 4) & 63, tap = i >> 10;
    float v = (ic < 15) ? w[oc*735 + ic*49 + tap] : 0.f;
    __nv_bfloat16 h = __float2bfloat16_rn(v);
    __nv_bfloat16 l = __float2bfloat16_rn(v - __bfloat162float(h));
    g_gwh[i] = h;
    g_gwl[i] = l;
}

__global__ void ew_convert(const float* __restrict__ w)   // [E][64][15][7][7]
{
    int i = blockIdx.x * 256 + threadIdx.x;
    if (i >= NEXP*49*64*16) return;
    int ic = i & 15, oc = (i >> 4) & 63, tap = (i >> 10) % 49, e = i / (49*1024);
    float v = (ic < 15) ? w[((e*64 + oc)*15 + ic)*49 + tap] : 0.f;
    __nv_bfloat16 h = __float2bfloat16_rn(v);
    __nv_bfloat16 l = __float2bfloat16_rn(v - __bfloat162float(h));
    g_ewh[i] = h;
    g_ewl[i] = l;
}

__global__ void w_convert(const float* __restrict__ w)    // head w1 [E][384][64][3][3]
{
    int i = blockIdx.x * 256 + threadIdx.x;
    if (i >= NEXP*384*64*9) return;
    int tap = i % 9;
    int r   = i / 9;
    int ic  = r % 64;
    int r2  = r / 64;
    int oc  = r2 % 384;
    int e   = r2 / 384;
    float v = w[i];
    __nv_bfloat16 h = __float2bfloat16_rn(v);
    __nv_bfloat16 l = __float2bfloat16_rn(v - __bfloat162float(h));
    int dst = ((e*9 + tap)*384 + oc)*64 + ic;
    g_wh[dst] = h;
    g_wl[dst] = l;
}

// =====================================================================
// Kernel 1: gating conv 7x7 s2 p3 (15->64) + BN + ReLU via bf16-split MMA
// CTA: 64 oc x 256 px, 8 warps (64x32 each). 49 taps, K=16 (15 ic + zero).
// =====================================================================
__global__ void __launch_bounds__(256)
gating_mma(const float* __restrict__ x,
           const float* __restrict__ gamma,
           const float* __restrict__ beta,
           const float* __restrict__ mean,
           const float* __restrict__ var)
{
    extern __shared__ char smem[];
    const uint32_t sb = smem_u32(smem);
    const int tid = threadIdx.x;
    const int wid = tid >> 5, lid = tid & 31;
    const int b   = blockIdx.y;
    const int p0  = blockIdx.x * 256;
    const int n0w = wid * 32;

    float acc[4][4][4];
    #pragma unroll
    for (int mt = 0; mt < 4; mt++)
        #pragma unroll
        for (int nt = 0; nt < 4; nt++)
            #pragma unroll
            for (int q = 0; q < 4; q++) acc[mt][nt][q] = 0.f;

    const int p  = p0 + tid;
    const int oh = p / GH, ow = p - oh*GH;
    const int ih0 = oh*2 - 3, iw0 = ow*2 - 3;
    const float* xb = x + (size_t)b * CIN * HIN * HIN;

    const int rr = lid & 7, sel = lid >> 3;
    const int arow = tid >> 2, apart = tid & 3;

    for (int tap = 0; tap < 49; tap++) {
        const int kh = tap / 7, kw = tap - 7*(tap/7);
        __syncthreads();

        // stage A (64 oc x 16 k), hi+lo
        {
            const __nv_bfloat16* sh = g_gwh + tap*1024 + arow*16 + apart*4;
            const __nv_bfloat16* sl = g_gwl + tap*1024 + arow*16 + apart*4;
            *(uint2*)(smem + SA_HI + arow*48 + apart*8) = *(const uint2*)sh;
            *(uint2*)(smem + SA_LO + arow*48 + apart*8) = *(const uint2*)sl;
        }
        // gather B (256 px x 16 k)
        {
            const int ih = ih0 + kh, iw = iw0 + kw;
            const bool ok = ((unsigned)ih < (unsigned)HIN) && ((unsigned)iw < (unsigned)HIN);
            const float* xq = xb + (size_t)ih*HIN + iw;
            uint32_t hp[8], lp[8];
            #pragma unroll
            for (int u = 0; u < 16; u += 2) {
                float v0 = (u < 15 && ok)   ? __ldg(xq + (size_t)u     * (HIN*HIN)) : 0.f;
                float v1 = (u + 1 < 15 && ok) ? __ldg(xq + (size_t)(u+1) * (HIN*HIN)) : 0.f;
                __nv_bfloat16 h0 = __float2bfloat16_rn(v0);
                __nv_bfloat16 h1 = __float2bfloat16_rn(v1);
                hp[u >> 1] = pkbf(h0, h1);
                __nv_bfloat16 l0 = __float2bfloat16_rn(v0 - __bfloat162float(h0));
                __nv_bfloat16 l1 = __float2bfloat16_rn(v1 - __bfloat162float(h1));
                lp[u >> 1] = pkbf(l0, l1);
            }
            *(uint4*)(smem + SB_HI + tid*48)      = make_uint4(hp[0], hp[1], hp[2], hp[3]);
            *(uint4*)(smem + SB_HI + tid*48 + 16) = make_uint4(hp[4], hp[5], hp[6], hp[7]);
            *(uint4*)(smem + SB_LO + tid*48)      = make_uint4(lp[0], lp[1], lp[2], lp[3]);
            *(uint4*)(smem + SB_LO + tid*48 + 16) = make_uint4(lp[4], lp[5], lp[6], lp[7]);
        }
        __syncthreads();

        uint32_t ah[4][4], al[4][4];
        #pragma unroll
        for (int mt = 0; mt < 4; mt++) {
            const uint32_t offA = (mt*16 + (sel & 1)*8 + rr)*48 + (sel >> 1)*16;
            LDSM4(ah[mt][0], ah[mt][1], ah[mt][2], ah[mt][3], sb + SA_HI + offA);
            LDSM4(al[mt][0], al[mt][1], al[mt][2], al[mt][3], sb + SA_LO + offA);
        }
        uint32_t bh[4][2], bl[4][2];
        #pragma unroll
        for (int pair = 0; pair < 2; pair++) {
            const uint32_t offB = (n0w + pair*16 + (sel >> 1)*8 + rr)*48 + (sel & 1)*16;
            LDSM4(bh[pair*2][0], bh[pair*2][1], bh[pair*2+1][0], bh[pair*2+1][1],
                  sb + SB_HI + offB);
            LDSM4(bl[pair*2][0], bl[pair*2][1], bl[pair*2+1][0], bl[pair*2+1][1],
                  sb + SB_LO + offB);
        }
        #pragma unroll
        for (int mt = 0; mt < 4; mt++)
            #pragma unroll
            for (int nt = 0; nt < 4; nt++) {
                MMA16816(acc[mt][nt], ah[mt], bh[nt][0], bh[nt][1]);
                MMA16816(acc[mt][nt], ah[mt], bl[nt][0], bl[nt][1]);
                MMA16816(acc[mt][nt], al[mt], bh[nt][0], bh[nt][1]);
            }
    }

    // epilogue: acc -> smem [64][256] -> BN+ReLU -> g_gate
    __syncthreads();
    float* epi = (float*)smem;
    {
        const int r  = lid >> 2;
        const int cc = (lid & 3) * 2;
        #pragma unroll
        for (int mt = 0; mt < 4; mt++)
            #pragma unroll
            for (int nt = 0; nt < 4; nt++) {
                const int m  = mt*16 + r;
                const int nn = n0w + nt*8 + cc;
                epi[m*256 + nn]         = acc[mt][nt][0];
                epi[m*256 + nn + 1]     = acc[mt][nt][1];
                epi[(m+8)*256 + nn]     = acc[mt][nt][2];
                epi[(m+8)*256 + nn + 1] = acc[mt][nt][3];
            }
    }
    __syncthreads();
    #pragma unroll
    for (int it = 0; it < 16; it++) {
        int i  = it*256 + tid;          // uint4 index
        int oc = i >> 6;
        int cx = (i & 63) * 4;
        float4 v = *(float4*)&epi[oc*256 + cx];
        float inv = gamma[oc] * rsqrtf(var[oc] + 1e-5f);
        float bia = beta[oc] - mean[oc]*inv;
        v.x = fmaxf(v.x*inv + bia, 0.f);
        v.y = fmaxf(v.y*inv + bia, 0.f);
        v.z = fmaxf(v.z*inv + bia, 0.f);
        v.w = fmaxf(v.w*inv + bia, 0.f);
        *(float4*)&g_gate[((size_t)(b*64 + oc))*(GH*GH) + p0 + cx] = v;
    }
}

// =====================================================================
// Kernel 4: expert conv1 7x7 s4 p3 (15->64) + bias + ReLU via bf16-split MMA
// =====================================================================
__global__ void __launch_bounds__(256)
expert_mma(const float* __restrict__ x,
           const float* __restrict__ eb)
{
    extern __shared__ char smem[];
    const uint32_t sb = smem_u32(smem);
    const int tid = threadIdx.x;
    const int wid = tid >> 5, lid = tid & 31;
    const int b   = blockIdx.y;
    const int e   = g_idx[b];
    const int p0  = blockIdx.x * 256;
    const int n0w = wid * 32;

    float acc[4][4][4];
    #pragma unroll
    for (int mt = 0; mt < 4; mt++)
        #pragma unroll
        for (int nt = 0; nt < 4; nt++)
            #pragma unroll
            for (int q = 0; q < 4; q++) acc[mt][nt][q] = 0.f;

    const int p  = p0 + tid;
    const int oh = p / PH, ow = p - oh*PH;
    const int ih0 = oh*4 - 3, iw0 = ow*4 - 3;
    const float* xb = x + (size_t)b * CIN * HIN * HIN;

    const int rr = lid & 7, sel = lid >> 3;
    const int arow = tid >> 2, apart = tid & 3;
    const __nv_bfloat16* ewh = g_ewh + (size_t)e * 49*1024;
    const __nv_bfloat16* ewl = g_ewl + (size_t)e * 49*1024;

    for (int tap = 0; tap < 49; tap++) {
        const int kh = tap / 7, kw = tap - 7*(tap/7);
        __syncthreads();

        {
            const __nv_bfloat16* sh = ewh + tap*1024 + arow*16 + apart*4;
            const __nv_bfloat16* sl = ewl + tap*1024 + arow*16 + apart*4;
            *(uint2*)(smem + SA_HI + arow*48 + apart*8) = *(const uint2*)sh;
            *(uint2*)(smem + SA_LO + arow*48 + apart*8) = *(const uint2*)sl;
        }
        {
            const int ih = ih0 + kh, iw = iw0 + kw;
            const bool ok = ((unsigned)ih < (unsigned)HIN) && ((unsigned)iw < (unsigned)HIN);
            const float* xq = xb + (size_t)ih*HIN + iw;
            uint32_t hp[8], lp[8];
            #pragma unroll
            for (int u = 0; u < 16; u += 2) {
                float v0 = (u < 15 && ok)     ? __ldg(xq + (size_t)u     * (HIN*HIN)) : 0.f;
                float v1 = (u + 1 < 15 && ok) ? __ldg(xq + (size_t)(u+1) * (HIN*HIN)) : 0.f;
                __nv_bfloat16 h0 = __float2bfloat16_rn(v0);
                __nv_bfloat16 h1 = __float2bfloat16_rn(v1);
                hp[u >> 1] = pkbf(h0, h1);
                __nv_bfloat16 l0 = __float2bfloat16_rn(v0 - __bfloat162float(h0));
                __nv_bfloat16 l1 = __float2bfloat16_rn(v1 - __bfloat162float(h1));
                lp[u >> 1] = pkbf(l0, l1);
            }
            *(uint4*)(smem + SB_HI + tid*48)      = make_uint4(hp[0], hp[1], hp[2], hp[3]);
            *(uint4*)(smem + SB_HI + tid*48 + 16) = make_uint4(hp[4], hp[5], hp[6], hp[7]);
            *(uint4*)(smem + SB_LO + tid*48)      = make_uint4(lp[0], lp[1], lp[2], lp[3]);
            *(uint4*)(smem + SB_LO + tid*48 + 16) = make_uint4(lp[4], lp[5], lp[6], lp[7]);
        }
        __syncthreads();

        uint32_t ah[4][4], al[4][4];
        #pragma unroll
        for (int mt = 0; mt < 4; mt++) {
            const uint32_t offA = (mt*16 + (sel & 1)*8 + rr)*48 + (sel >> 1)*16;
            LDSM4(ah[mt][0], ah[mt][1], ah[mt][2], ah[mt][3], sb + SA_HI + offA);
            LDSM4(al[mt][0], al[mt][1], al[mt][2], al[mt][3], sb + SA_LO + offA);
        }
        uint32_t bh[4][2], bl[4][2];
        #pragma unroll
        for (int pair = 0; pair < 2; pair++) {
            const uint32_t offB = (n0w + pair*16 + (sel >> 1)*8 + rr)*48 + (sel & 1)*16;
            LDSM4(bh[pair*2][0], bh[pair*2][1], bh[pair*2+1][0], bh[pair*2+1][1],
                  sb + SB_HI + offB);
            LDSM4(bl[pair*2][0], bl[pair*2][1], bl[pair*2+1][0], bl[pair*2+1][1],
                  sb + SB_LO + offB);
        }
        #pragma unroll
        for (int mt = 0; mt < 4; mt++)
            #pragma unroll
            for (int nt = 0; nt < 4; nt++) {
                MMA16816(acc[mt][nt], ah[mt], bh[nt][0], bh[nt][1]);
                MMA16816(acc[mt][nt], ah[mt], bl[nt][0], bl[nt][1]);
                MMA16816(acc[mt][nt], al[mt], bh[nt][0], bh[nt][1]);
            }
    }

    __syncthreads();
    float* epi = (float*)smem;
    {
        const int r  = lid >> 2;
        const int cc = (lid & 3) * 2;
        #pragma unroll
        for (int mt = 0; mt < 4; mt++)
            #pragma unroll
            for (int nt = 0; nt < 4; nt++) {
                const int m  = mt*16 + r;
                const int nn = n0w + nt*8 + cc;
                epi[m*256 + nn]         = acc[mt][nt][0];
                epi[m*256 + nn + 1]     = acc[mt][nt][1];
                epi[(m+8)*256 + nn]     = acc[mt][nt][2];
                epi[(m+8)*256 + nn + 1] = acc[mt][nt][3];
            }
    }
    __syncthreads();
    const float* bb = eb + e*64;
    #pragma unroll
    for (int it = 0; it < 16; it++) {
        int i  = it*256 + tid;
        int oc = i >> 6;
        int cx = (i & 63) * 4;
        float4 v = *(float4*)&epi[oc*256 + cx];
        float bias = bb[oc];
        v.x = fmaxf(v.x + bias, 0.f);
        v.y = fmaxf(v.y + bias, 0.f);
        v.z = fmaxf(v.z + bias, 0.f);
        v.w = fmaxf(v.w + bias, 0.f);
        *(float4*)&g_y1[((size_t)(b*64 + oc))*(PH*PH) + p0 + cx] = v;
    }
}

// =====================================================================
// Kernel 2: maxpool 3x3 s2 p1 + spatial mean
// =====================================================================
__global__ void pool_mean()
{
    const int bc = blockIdx.x;
    const float* src = g_gate + (size_t)bc * GH * GH;
    const int tid = threadIdx.x;
    float sum = 0.f;
    for (int p = tid; p < PH*PH; p += 256) {
        int ph = p / PH, pw = p - ph*PH;
        float m = -1e30f;
        #pragma unroll
        for (int r = 0; r < 3; r++) {
            int ih = 2*ph - 1 + r;
            if ((unsigned)ih >= (unsigned)GH) continue;
            #pragma unroll
            for (int c = 0; c < 3; c++) {
                int iw = 2*pw - 1 + c;
                if ((unsigned)iw >= (unsigned)GH) continue;
                m = fmaxf(m, src[ih*GH + iw]);
            }
        }
        sum += m;
    }
    __shared__ float red[256];
    red[tid] = sum;
    __syncthreads();
    for (int s = 128; s > 0; s >>= 1) {
        if (tid < s) red[tid] += red[tid + s];
        __syncthreads();
    }
    if (tid == 0) g_feat[bc] = red[0] / (float)(PH*PH);
}

// =====================================================================
// Kernel 3: logits, argmax, aux loss
// =====================================================================
__global__ void gate_head(const float* __restrict__ fcw,
                          const float* __restrict__ fcb,
                          float* __restrict__ out, int out_size)
{
    __shared__ float lg[B][NEXP];
    __shared__ float proxy[NEXP];
    __shared__ int   cnt[NEXP];
    const int t = threadIdx.x;

    if (t < NEXP) { proxy[t] = 0.f; cnt[t] = 0; }
    if (t < B*NEXP) {
        int b = t / NEXP, e = t - b*NEXP;
        float s = fcb[e];
        const float* f = g_feat + b*64;
        const float* wr = fcw + e*64;
        for (int c = 0; c < 64; c++) s += f[c]*wr[c];
        lg[b][e] = s;
    }
    __syncthreads();
    if (t < B) {
        float l0 = lg[t][0], l1 = lg[t][1], l2 = lg[t][2];
        int am = 0; float bm = l0;
        if (l1 > bm) { bm = l1; am = 1; }
        if (l2 > bm) { bm = l2; am = 2; }
        g_idx[t] = am;
        atomicAdd(&cnt[am], 1);
        float m = bm;
        float e0 = expf(l0 - m), e1 = expf(l1 - m), e2 = expf(l2 - m);
        float s = e0 + e1 + e2;
        atomicAdd(&proxy[0], e0/s);
        atomicAdd(&proxy[1], e1/s);
        atomicAdd(&proxy[2], e2/s);
    }
    __syncthreads();
    if (t == 0 && out_size > N_OUT) {
        float aux = 0.f;
        for (int e = 0; e < NEXP; e++)
            aux += ((float)cnt[e] / (float)B) * (proxy[e] / (float)B);
        out[N_OUT] = 0.01f * (aux * (float)NEXP);
    }
}

// =====================================================================
// Kernel 5: head conv1 3x3 s1 p1 (64->384) via mma.sync bf16 split (R4 verified)
// =====================================================================
__global__ void __launch_bounds__(256)
head_conv1_mma(const float* __restrict__ hb1)
{
    extern __shared__ char smem[];
    const uint32_t sb = smem_u32(smem);
    const int tid = threadIdx.x;
    const int wid = tid >> 5, lid = tid & 31;
    const int b   = blockIdx.z;
    const int ocb = blockIdx.y;
    const int p0  = blockIdx.x * 128;
    const int e   = g_idx[b];

    const int warpM = wid >> 2, warpN = wid & 3;
    const int m0w = warpM * 64, n0w = warpN * 32;

    float acc[4][4][4];
    #pragma unroll
    for (int mt = 0; mt < 4; mt++)
        #pragma unroll
        for (int nt = 0; nt < 4; nt++)
            #pragma unroll
            for (int q = 0; q < 4; q++) acc[mt][nt][q] = 0.f;

    const int n = tid & 127;
    const int g = tid >> 7;
    const int p = p0 + n;
    const int pr = p / 96;
    const int pc = p - pr*96;
    const float* y1b = g_y1 + (size_t)b * 64 * PH*PH;

    const int rr  = lid & 7;
    const int sel = lid >> 3;

    for (int tap = 0; tap < 9; tap++) {
        const int kh = tap / 3, kw = tap - 3*(tap/3);
        __syncthreads();

        {
            const __nv_bfloat16* whb = g_wh + ((size_t)((e*9 + tap)*384 + ocb*128))*64;
            const __nv_bfloat16* wlb = g_wl + ((size_t)((e*9 + tap)*384 + ocb*128))*64;
            #pragma unroll
            for (int it = 0; it < 8; it++) {
                int idx = it*256 + tid;
                int s   = idx >> 10;
                int r   = idx & 1023;
                int oc  = r >> 3;
                int ch  = r & 7;
                const __nv_bfloat16* src = (s ? wlb : whb) + oc*64 + ch*8;
                uint4 v = *(const uint4*)src;
                *(uint4*)(smem + s*16384 + SW128((uint32_t)(oc*128 + ch*16))) = v;
            }
        }

        {
            const int ri = pr + kh - 1, ci = pc + kw - 1;
            const bool ok = ((unsigned)ri < 96u) && ((unsigned)ci < 96u);
            const float* yq = y1b + (size_t)ri*96 + ci;
            #pragma unroll
            for (int j = 0; j < 4; j++) {
                const int ic0 = g*32 + j*8;
                float v[8];
                #pragma unroll
                for (int u = 0; u < 8; u++)
                    v[u] = ok ? __ldg(yq + (size_t)(ic0 + u) * (PH*PH)) : 0.f;
                __nv_bfloat16 h[8];
                uint32_t hp[4], lp[4];
                #pragma unroll
                for (int u = 0; u < 8; u++) h[u] = __float2bfloat16_rn(v[u]);
                #pragma unroll
                for (int u = 0; u < 4; u++) hp[u] = pkbf(h[2*u], h[2*u+1]);
                #pragma unroll
                for (int u = 0; u < 8; u += 2) {
                    __nv_bfloat16 l0 = __float2bfloat16_rn(v[u]   - __bfloat162float(h[u]));
                    __nv_bfloat16 l1 = __float2bfloat16_rn(v[u+1] - __bfloat162float(h[u+1]));
                    lp[u>>1] = pkbf(l0, l1);
                }
                const uint32_t off = SW128((uint32_t)(n*128 + ic0*2));
                *(uint4*)(smem + 32768 + off) = make_uint4(hp[0], hp[1], hp[2], hp[3]);
                *(uint4*)(smem + 49152 + off) = make_uint4(lp[0], lp[1], lp[2], lp[3]);
            }
        }
        __syncthreads();

        #pragma unroll
        for (int kc = 0; kc < 4; kc++) {
            const int k0b = kc*32;

            uint32_t ah[4][4], al[4][4];
            {
                const int arow = m0w + (sel & 1)*8 + rr;
                const int akb  = k0b + ((sel >> 1)*8)*2;
                #pragma unroll
                for (int mt = 0; mt < 4; mt++) {
                    uint32_t off = SW128((uint32_t)((arow + mt*16)*128 + akb));
                    LDSM4(ah[mt][0], ah[mt][1], ah[mt][2], ah[mt][3], sb + off);
                    LDSM4(al[mt][0], al[mt][1], al[mt][2], al[mt][3], sb + 16384 + off);
                }
            }

            uint32_t bh[4][2], bl[4][2];
            {
                const int brow = n0w + (sel >> 1)*8 + rr;
                const int bkb  = k0b + ((sel & 1)*8)*2;
                #pragma unroll
                for (int pair = 0; pair < 2; pair++) {
                    uint32_t off = SW128((uint32_t)((brow + pair*16)*128 + bkb));
                    LDSM4(bh[pair*2][0], bh[pair*2][1], bh[pair*2+1][0], bh[pair*2+1][1],
                          sb + 32768 + off);
                    LDSM4(bl[pair*2][0], bl[pair*2][1], bl[pair*2+1][0], bl[pair*2+1][1],
                          sb + 49152 + off);
                }
            }

            #pragma unroll
            for (int mt = 0; mt < 4; mt++)
                #pragma unroll
                for (int nt = 0; nt < 4; nt++) {
                    MMA16816(acc[mt][nt], ah[mt], bh[nt][0], bh[nt][1]);
                    MMA16816(acc[mt][nt], ah[mt], bl[nt][0], bl[nt][1]);
                    MMA16816(acc[mt][nt], al[mt], bh[nt][0], bh[nt][1]);
                }
        }
    }

    __syncthreads();
    float* epi = (float*)smem;
    {
        const int r  = lid >> 2;
        const int cc = (lid & 3) * 2;
        #pragma unroll
        for (int mt = 0; mt < 4; mt++)
            #pragma unroll
            for (int nt = 0; nt < 4; nt++) {
                const int m  = m0w + mt*16 + r;
                const int nn = n0w + nt*8 + cc;
                epi[m*128 + nn]         = acc[mt][nt][0];
                epi[m*128 + nn + 1]     = acc[mt][nt][1];
                epi[(m+8)*128 + nn]     = acc[mt][nt][2];
                epi[(m+8)*128 + nn + 1] = acc[mt][nt][3];
            }
    }
    __syncthreads();
    {
        const float* bb = hb1 + e*384 + ocb*128;
        #pragma unroll
        for (int it = 0; it < 16; it++) {
            int i  = it*256 + tid;
            int oc = i >> 5;
            int cx = (i & 31) * 4;
            float4 v = *(float4*)&epi[oc*128 + cx];
            float bias = bb[oc];
            v.x = fmaxf(v.x + bias, 0.f);
            v.y = fmaxf(v.y + bias, 0.f);
            v.z = fmaxf(v.z + bias, 0.f);
            v.w = fmaxf(v.w + bias, 0.f);
            *(float4*)&g_y2[((size_t)(b*384 + ocb*128 + oc))*(PH*PH) + p0 + cx] = v;
        }
    }
}

// =====================================================================
// Kernel 6: grouped 1x1 conv (384 -> 6, groups=3) + bias
// =====================================================================
__global__ void head_conv2(const float* __restrict__ hw2,
                           const float* __restrict__ hb2,
                           float* __restrict__ out)
{
    const int b = blockIdx.z;
    const int g = blockIdx.y;
    const int e = g_idx[b];
    const int tid = threadIdx.x;
    const int p = blockIdx.x * 256 + tid;

    __shared__ float w0s[128], w1s[128];
    if (tid < 128) {
        w0s[tid] = hw2[(e*6 + 2*g)    *128 + tid];
        w1s[tid] = hw2[(e*6 + 2*g + 1)*128 + tid];
    }
    __syncthreads();

    float a0 = hb2[e*6 + 2*g];
    float a1 = hb2[e*6 + 2*g + 1];
    const float* yp = g_y2 + ((size_t)b*384 + g*128) * (PH*PH) + p;
    #pragma unroll 8
    for (int ic = 0; ic < 128; ic++) {
        float v = yp[(size_t)ic * (PH*PH)];
        a0 += v * w0s[ic];
        a1 += v * w1s[ic];
    }
    out[((size_t)b*6 + 2*g)    *(PH*PH) + p] = a0;
    out[((size_t)b*6 + 2*g + 1)*(PH*PH) + p] = a1;
}

// =====================================================================
// launcher
// =====================================================================
extern "C" void kernel_launch(void* const* d_in, const int* in_sizes, int n_in,
                              void* d_out, int out_size)
{
    const float* x        = (const float*)d_in[0];
    const float* g_conv_w = (const float*)d_in[1];
    const float* g_gamma  = (const float*)d_in[2];
    const float* g_beta   = (const float*)d_in[3];
    const float* g_mean   = (const float*)d_in[4];
    const float* g_var    = (const float*)d_in[5];
    const float* g_fc_w   = (const float*)d_in[6];
    const float* g_fc_b   = (const float*)d_in[7];
    const float* e_conv1_w = (const float*)d_in[8];
    const float* e_conv1_b = (const float*)d_in[9];
    const float* e_head_w1 = (const float*)d_in[10];
    const float* e_head_b1 = (const float*)d_in[11];
    const float* e_head_w2 = (const float*)d_in[12];
    const float* e_head_b2 = (const float*)d_in[13];
    float* out = (float*)d_out;

    cudaFuncSetAttribute(head_conv1_mma,
                         cudaFuncAttributeMaxDynamicSharedMemorySize, 65536);
    cudaFuncSetAttribute(gating_mma,
                         cudaFuncAttributeMaxDynamicSharedMemorySize, 65536);
    cudaFuncSetAttribute(expert_mma,
                         cudaFuncAttributeMaxDynamicSharedMemorySize, 65536);

    gw_convert<<<(49*64*16 + 255)/256, 256>>>(g_conv_w);
    ew_convert<<<(NEXP*49*64*16 + 255)/256, 256>>>(e_conv1_w);
    w_convert<<<(NEXP*384*64*9 + 255)/256, 256>>>(e_head_w1);

    dim3 ggate(GH*GH/256, B);                    // 144, 16
    gating_mma<<<ggate, 256, 65536>>>(x, g_gamma, g_beta, g_mean, g_var);

    pool_mean<<<B*64, 256>>>();

    gate_head<<<1, 64>>>(g_fc_w, g_fc_b, out, out_size);

    dim3 gexp(PH*PH/256, B);                     // 36, 16
    expert_mma<<<gexp, 256, 65536>>>(x, e_conv1_b);

    dim3 ghead(PH*PH/128, 3, B);                 // 72, 3, 16
    head_conv1_mma<<<ghead, 256, 65536>>>(e_head_b1);

    dim3 gh2(PH*PH/256, 3, B);                   // 36, 3, 16
    head_conv2<<<gh2, 256>>>(e_head_w2, e_head_b2, out);
}